// round 7
// baseline (speedup 1.0000x reference)
#include <cuda_runtime.h>
#include <cuda_fp16.h>
#include <cstdint>

#define D_DIM 512
#define C_DIM 1024
#define M_TILE 64
#define NTHREADS 512

// smem layout (bytes)
#define QOFF   0            // 64 x 512 fp16, 8 panels of (64 rows x 128B), SW128; reused as GEMM2 stages 0..3
#define WOFF   65536        // 64 x 1024 fp16, 16 panels of (64 rows x 128B), SW128
#define SBOFF  196608       // 2 x 16384: GEMM1 staging; GEMM2 stages 4..5
#define REDOFF 229376       // 512 floats
#define INVOFF 231424       // 64 floats
#define SMEM_BYTES 231680

// ---- small device scratch (3 MiB total) ----
__device__ __half g_Kh[C_DIM * D_DIM];   // normalized keys fp16 (row-major, K-major)
__device__ __half g_Vt[C_DIM * C_DIM];   // val transposed fp16: g_Vt[n*C+k] = val[k*C+n]

// ---- helpers ----
__device__ __forceinline__ uint32_t smem_u32(const void* p) {
    uint32_t a;
    asm("{ .reg .u64 t; cvta.to.shared.u64 t, %1; cvt.u32.u64 %0, t; }" : "=r"(a) : "l"(p));
    return a;
}
#define SWZ(x) ((x) ^ (((x) >> 3) & 0x70))

__device__ __forceinline__ void cp16(uint32_t s, const void* g) {
    asm volatile("cp.async.cg.shared.global [%0], [%1], 16;" :: "r"(s), "l"(g));
}
#define CP_COMMIT() asm volatile("cp.async.commit_group;" ::: "memory")
#define CP_WAIT1()  asm volatile("cp.async.wait_group 1;" ::: "memory")
#define CP_WAIT4()  asm volatile("cp.async.wait_group 4;" ::: "memory")
#define CP_WAIT0()  asm volatile("cp.async.wait_group 0;" ::: "memory")

__device__ __forceinline__ void ldsm4(unsigned r[4], uint32_t a) {
    asm volatile("ldmatrix.sync.aligned.m8n8.x4.shared.b16 {%0,%1,%2,%3}, [%4];"
                 : "=r"(r[0]), "=r"(r[1]), "=r"(r[2]), "=r"(r[3]) : "r"(a));
}
__device__ __forceinline__ void mma16816(float c[4], const unsigned a[4], const unsigned b[2]) {
    asm volatile(
        "mma.sync.aligned.m16n8k16.row.col.f32.f16.f16.f32 "
        "{%0,%1,%2,%3}, {%4,%5,%6,%7}, {%8,%9}, {%0,%1,%2,%3};\n"
        : "+f"(c[0]), "+f"(c[1]), "+f"(c[2]), "+f"(c[3])
        : "r"(a[0]), "r"(a[1]), "r"(a[2]), "r"(a[3]), "r"(b[0]), "r"(b[1]));
}

// sharp(x) = sigmoid(10x-5) + sigmoid(-10x-5)
__device__ __forceinline__ float sharp_fn(float x) {
    const float E = 148.4131591f;      // e^5
    const float E2p1 = 22027.4658f;    // e^10 + 1
    float u = __expf(10.f * x);
    float eu = E * u;
    float num = fmaf(eu, u, fmaf(2.f, u, E));
    float den = fmaf(eu, u, fmaf(E2p1, u, E));
    return __fdividef(num, den);
}

// stage one B chunk: 128 rows x 64 cols fp16 (512 threads)
__device__ __forceinline__ void fillB(const __half* __restrict__ gsrc, int ldb,
                                      uint32_t dst, int tid) {
#pragma unroll
    for (int it = 0; it < 2; ++it) {
        int idx = it * NTHREADS + tid;
        int r = idx >> 3, c = idx & 7;
        cp16(dst + SWZ(r * 128 + c * 16), gsrc + (size_t)r * ldb + c * 8);
    }
}

// GEMM2 rotating stage address (6 stages: 4 in Q region, 2 in SBOFF)
__device__ __forceinline__ uint32_t stage_off(int u) {
    int m = u % 6;
    return (m < 4) ? (uint32_t)(QOFF + m * 16384)
                   : (uint32_t)(SBOFF + (m - 4) * 16384);
}

// ---- prep kernels ----
__global__ void normalize_key_kernel(const float* __restrict__ key) {
    const int r = blockIdx.x;
    const int tid = threadIdx.x;  // 128
    const float* kr = key + (size_t)r * D_DIM;
    float v[4];
    float ss = 0.f;
#pragma unroll
    for (int i = 0; i < 4; ++i) { v[i] = kr[tid + i * 128]; ss += v[i] * v[i]; }
    __shared__ float ws[4];
    __shared__ float sinv;
#pragma unroll
    for (int o = 16; o > 0; o >>= 1) ss += __shfl_down_sync(0xffffffffu, ss, o);
    if ((tid & 31) == 0) ws[tid >> 5] = ss;
    __syncthreads();
    if (tid == 0) sinv = rsqrtf(ws[0] + ws[1] + ws[2] + ws[3] + 1e-12f);
    __syncthreads();
    const float iv = sinv;
#pragma unroll
    for (int i = 0; i < 4; ++i)
        g_Kh[(size_t)r * D_DIM + tid + i * 128] = __float2half(v[i] * iv);
}

__global__ void transpose_val_kernel(const float* __restrict__ val) {
    __shared__ float tile[32][33];
    const int ko = blockIdx.x * 32;
    const int no = blockIdx.y * 32;
    const int tx = threadIdx.x, ty = threadIdx.y;  // (32, 8)
#pragma unroll
    for (int j = 0; j < 32; j += 8)
        tile[ty + j][tx] = val[(size_t)(ko + ty + j) * C_DIM + no + tx];
    __syncthreads();
#pragma unroll
    for (int j = 0; j < 32; j += 8)
        g_Vt[(size_t)(no + ty + j) * C_DIM + ko + tx] = __float2half(tile[tx][ty + j]);
}

// ---- fused main kernel: 512 threads, 16 warps, warp tile 16x32 ----
__global__ __launch_bounds__(NTHREADS, 1)
void fused_kv_kernel(const float* __restrict__ query, float* __restrict__ out) {
    extern __shared__ char smem[];
    const uint32_t sb = smem_u32(smem);
    float* red = (float*)(smem + REDOFF);
    float* inv = (float*)(smem + INVOFF);

    const int tid  = threadIdx.x;
    const int lane = tid & 31;
    const int wid  = tid >> 5;
    const int wm   = wid >> 2;          // 0..3 (16 rows each)
    const int wn   = wid & 3;           // 0..3 (32 cols each within 128-chunk)
    const int g    = lane >> 2;         // 0..7
    const int tig  = lane & 3;          // 0..3
    const int lrow = lane & 15;
    const int hs   = lane >> 4;         // k-half selector
    const int row0 = blockIdx.x * M_TILE;

    // ---- Step 0: load + l2-normalize Q tile into swizzled smem ----
    {
        const int r = tid >> 3;           // 0..63
        const int p = tid & 7;            // panel p (cols p*64 .. p*64+63)
        const float* qrow = query + (size_t)(row0 + r) * D_DIM + p * 64;
        char* pb = smem + QOFF + p * 8192;
        float ss = 0.f;
#pragma unroll 4
        for (int j = 0; j < 64; j += 4) {
            float4 v = *(const float4*)(qrow + j);
            ss += v.x * v.x + v.y * v.y + v.z * v.z + v.w * v.w;
            int b = r * 128 + j * 2;
            *(__half2*)(pb + SWZ(b))     = __floats2half2_rn(v.x, v.y);
            *(__half2*)(pb + SWZ(b + 4)) = __floats2half2_rn(v.z, v.w);
        }
        red[tid] = ss;
        __syncthreads();
        if (tid < M_TILE) {
            float s = 0.f;
#pragma unroll
            for (int j = 0; j < 8; ++j) s += red[tid * 8 + j];
            inv[tid] = rsqrtf(s + 1e-12f);
        }
        __syncthreads();
        const float qin = inv[r];
#pragma unroll 8
        for (int b = 0; b < 128; b += 4) {
            __half2* hp = (__half2*)(pb + SWZ(r * 128 + b));
            float2 f = __half22float2(*hp);
            *hp = __floats2half2_rn(f.x * qin, f.y * qin);
        }
    }
    __syncthreads();

    float acc[4][4];

    // ---- GEMM1: W = sharp(Qn @ Kn^T), 64 iterations (8 nc x 8 kc), 2-stage ----
    fillB(g_Kh, D_DIM, sb + SBOFF, tid);
    CP_COMMIT();
    fillB(g_Kh + 64, D_DIM, sb + SBOFF + 16384, tid);
    CP_COMMIT();
    CP_WAIT1();
    __syncthreads();

#pragma unroll 1
    for (int t = 0; t < 64; ++t) {
        const int nc = t >> 3, kc = t & 7;
        if (kc == 0) {
#pragma unroll
            for (int ni = 0; ni < 4; ++ni)
#pragma unroll
                for (int e = 0; e < 4; ++e) acc[ni][e] = 0.f;
        }
        const uint32_t sB = sb + SBOFF + (t & 1) * 16384;
        const uint32_t sA = sb + QOFF + kc * 8192;
#pragma unroll
        for (int ks = 0; ks < 4; ++ks) {
            unsigned a[4], b[4][2];
            ldsm4(a, sA + SWZ((wm * 16 + lrow) * 128 + ks * 32 + hs * 16));
#pragma unroll
            for (int pr = 0; pr < 2; ++pr) {
                unsigned r4[4];
                int nr = wn * 32 + pr * 16 + lrow;
                ldsm4(r4, sB + SWZ(nr * 128 + ks * 32 + hs * 16));
                b[pr * 2][0] = r4[0]; b[pr * 2 + 1][0] = r4[1];
                b[pr * 2][1] = r4[2]; b[pr * 2 + 1][1] = r4[3];
            }
#pragma unroll
            for (int ni = 0; ni < 4; ++ni)
                mma16816(acc[ni], a, b[ni]);
        }
        if (kc == 7) {
            // sharpen -> W smem
#pragma unroll
            for (int ni = 0; ni < 4; ++ni) {
                int rr = wm * 16 + g;
                int cc = nc * 128 + wn * 32 + ni * 8 + tig * 2;
                int panel = cc >> 6, c6 = cc & 63;
                char* base = smem + WOFF + panel * 8192;
                *(__half2*)(base + SWZ(rr * 128 + c6 * 2)) =
                    __floats2half2_rn(sharp_fn(acc[ni][0]), sharp_fn(acc[ni][1]));
                *(__half2*)(base + SWZ((rr + 8) * 128 + c6 * 2)) =
                    __floats2half2_rn(sharp_fn(acc[ni][2]), sharp_fn(acc[ni][3]));
            }
        }
        __syncthreads();
        if (t + 2 < 64) {
            int u = t + 2;
            fillB(g_Kh + (size_t)((u >> 3) * 128) * D_DIM + (u & 7) * 64, D_DIM,
                  sb + SBOFF + (u & 1) * 16384, tid);
        }
        CP_COMMIT();
        CP_WAIT1();
        __syncthreads();
    }
    CP_WAIT0();
    __syncthreads();

    // ---- rowsum of W -> inv ----
    {
        const int r = tid >> 3, p = tid & 7;
        float s = 0.f;
#pragma unroll
        for (int q = 0; q < 2; ++q) {
            const uint4* rp = (const uint4*)(smem + WOFF + (p * 2 + q) * 8192 + r * 128);
#pragma unroll
            for (int i = 0; i < 8; ++i) {
                uint4 v = rp[i];
                const __half2* h2 = (const __half2*)&v;
#pragma unroll
                for (int j = 0; j < 4; ++j) {
                    float2 f = __half22float2(h2[j]);
                    s += f.x + f.y;
                }
            }
        }
        red[tid] = s;
        __syncthreads();
        if (tid < M_TILE) {
            float t2 = 0.f;
#pragma unroll
            for (int j = 0; j < 8; ++j) t2 += red[tid * 8 + j];
            inv[tid] = 1.f / t2;
        }
        __syncthreads();
    }

    // ---- GEMM2: out = (1/rowsum) * W @ val, 128 iterations (8 nc x 16 kc) ----
    // 6 rotating 16KB stages (Q region + SBOFF), single sync per iteration
#pragma unroll 1
    for (int s = 0; s < 5; ++s) {
        fillB(g_Vt + (size_t)((s >> 4) * 128) * C_DIM + (s & 15) * 64, C_DIM,
              sb + stage_off(s), tid);
        CP_COMMIT();
    }
    CP_WAIT4();
    __syncthreads();

#pragma unroll 1
    for (int t = 0; t < 128; ++t) {
        const int nc = t >> 4, kc = t & 15;
        if (kc == 0) {
#pragma unroll
            for (int ni = 0; ni < 4; ++ni)
#pragma unroll
                for (int e = 0; e < 4; ++e) acc[ni][e] = 0.f;
        }
        {
            int u = t + 5;
            if (u < 128)
                fillB(g_Vt + (size_t)((u >> 4) * 128) * C_DIM + (u & 15) * 64, C_DIM,
                      sb + stage_off(u), tid);
            CP_COMMIT();
        }
        const uint32_t sB = sb + stage_off(t);
        const uint32_t sA = sb + WOFF + kc * 8192;
#pragma unroll
        for (int ks = 0; ks < 4; ++ks) {
            unsigned a[4], b[4][2];
            ldsm4(a, sA + SWZ((wm * 16 + lrow) * 128 + ks * 32 + hs * 16));
#pragma unroll
            for (int pr = 0; pr < 2; ++pr) {
                unsigned r4[4];
                int nr = wn * 32 + pr * 16 + lrow;
                ldsm4(r4, sB + SWZ(nr * 128 + ks * 32 + hs * 16));
                b[pr * 2][0] = r4[0]; b[pr * 2 + 1][0] = r4[1];
                b[pr * 2][1] = r4[2]; b[pr * 2 + 1][1] = r4[3];
            }
#pragma unroll
            for (int ni = 0; ni < 4; ++ni)
                mma16816(acc[ni], a, b[ni]);
        }
        if (kc == 15) {
#pragma unroll
            for (int ni = 0; ni < 4; ++ni) {
                int rr = wm * 16 + g;
                int cc = nc * 128 + wn * 32 + ni * 8 + tig * 2;
                float i0 = inv[rr], i8 = inv[rr + 8];
                *(float2*)(out + (size_t)(row0 + rr) * C_DIM + cc) =
                    make_float2(acc[ni][0] * i0, acc[ni][1] * i0);
                *(float2*)(out + (size_t)(row0 + rr + 8) * C_DIM + cc) =
                    make_float2(acc[ni][2] * i8, acc[ni][3] * i8);
            }
        }
        CP_WAIT4();
        __syncthreads();
    }
}

// ---------------------------------------------------------------------------
extern "C" void kernel_launch(void* const* d_in, const int* in_sizes, int n_in,
                              void* d_out, int out_size) {
    const float* query = (const float*)d_in[0];
    const float* key   = (const float*)d_in[1];
    const float* val   = (const float*)d_in[2];
    float* out = (float*)d_out;

    const int B = in_sizes[0] / D_DIM;

    normalize_key_kernel<<<C_DIM, 128>>>(key);
    transpose_val_kernel<<<dim3(C_DIM / 32, C_DIM / 32), dim3(32, 8)>>>(val);

    cudaFuncSetAttribute(fused_kv_kernel,
                         cudaFuncAttributeMaxDynamicSharedMemorySize, SMEM_BYTES);
    fused_kv_kernel<<<B / M_TILE, NTHREADS, SMEM_BYTES>>>(query, out);
}

// round 8
// speedup vs baseline: 1.2893x; 1.2893x over previous
#include <cuda_runtime.h>
#include <cuda_fp16.h>
#include <cstdint>

#define D_DIM 512
#define C_DIM 1024
#define M_TILE 64
#define NTHREADS 256

// smem layout (bytes)
#define QOFF   0            // 64 x 512 fp16, 8 panels (64r x 128B) SW128; reused as GEMM2 stages 0,1
#define WOFF   65536        // 64 x 1024 fp16, 16 panels (64r x 128B) SW128
#define SBOFF  196608       // GEMM1: 2 x 16KB stages; GEMM2: stage 2 (32KB)
#define REDOFF 229376       // 256 floats
#define INVOFF 230400       // 64 floats
#define SMEM_BYTES 230656
#define ST2SZ  32768        // GEMM2 stage: 256 rows x 64 cols fp16

// ---- small device scratch (3 MiB total) ----
__device__ __half g_Kh[C_DIM * D_DIM];   // normalized keys fp16
__device__ __half g_Vt[C_DIM * C_DIM];   // val transposed fp16: g_Vt[n*C+k] = val[k*C+n]

// ---- helpers ----
__device__ __forceinline__ uint32_t smem_u32(const void* p) {
    uint32_t a;
    asm("{ .reg .u64 t; cvta.to.shared.u64 t, %1; cvt.u32.u64 %0, t; }" : "=r"(a) : "l"(p));
    return a;
}
#define SWZ(x) ((x) ^ (((x) >> 3) & 0x70))

__device__ __forceinline__ void cp16(uint32_t s, const void* g) {
    asm volatile("cp.async.cg.shared.global [%0], [%1], 16;" :: "r"(s), "l"(g));
}
#define CP_COMMIT() asm volatile("cp.async.commit_group;" ::: "memory")
#define CP_WAIT1()  asm volatile("cp.async.wait_group 1;" ::: "memory")
#define CP_WAIT0()  asm volatile("cp.async.wait_group 0;" ::: "memory")

__device__ __forceinline__ void ldsm4(unsigned r[4], uint32_t a) {
    asm volatile("ldmatrix.sync.aligned.m8n8.x4.shared.b16 {%0,%1,%2,%3}, [%4];"
                 : "=r"(r[0]), "=r"(r[1]), "=r"(r[2]), "=r"(r[3]) : "r"(a));
}
__device__ __forceinline__ void mma16816(float c[4], const unsigned a[4], const unsigned b[2]) {
    asm volatile(
        "mma.sync.aligned.m16n8k16.row.col.f32.f16.f16.f32 "
        "{%0,%1,%2,%3}, {%4,%5,%6,%7}, {%8,%9}, {%0,%1,%2,%3};\n"
        : "+f"(c[0]), "+f"(c[1]), "+f"(c[2]), "+f"(c[3])
        : "r"(a[0]), "r"(a[1]), "r"(a[2]), "r"(a[3]), "r"(b[0]), "r"(b[1]));
}

// sharp(x) = sigmoid(10x-5) + sigmoid(-10x-5)
__device__ __forceinline__ float sharp_fn(float x) {
    const float E = 148.4131591f;      // e^5
    const float E2p1 = 22027.4658f;    // e^10 + 1
    float u = __expf(10.f * x);
    float eu = E * u;
    float num = fmaf(eu, u, fmaf(2.f, u, E));
    float den = fmaf(eu, u, fmaf(E2p1, u, E));
    return __fdividef(num, den);
}

// GEMM1 stage: 128 rows x 64 cols fp16 (256 threads)
__device__ __forceinline__ void fillB(const __half* __restrict__ gsrc, int ldb,
                                      uint32_t dst, int tid) {
#pragma unroll
    for (int it = 0; it < 4; ++it) {
        int idx = it * NTHREADS + tid;
        int r = idx >> 3, c = idx & 7;
        cp16(dst + SWZ(r * 128 + c * 16), gsrc + (size_t)r * ldb + c * 8);
    }
}

// GEMM2 stage: 256 rows x 64 cols fp16 (256 threads)
__device__ __forceinline__ void fillB2(const __half* __restrict__ gsrc, int ldb,
                                       uint32_t dst, int tid) {
#pragma unroll
    for (int it = 0; it < 8; ++it) {
        int idx = it * NTHREADS + tid;
        int r = idx >> 3, c = idx & 7;
        cp16(dst + SWZ(r * 128 + c * 16), gsrc + (size_t)r * ldb + c * 8);
    }
}

// GEMM2 rotating stage base (3 distinct 32KB buffers)
__device__ __forceinline__ uint32_t stage2_off(int u) {
    int m = u % 3;
    return (m < 2) ? (uint32_t)(QOFF + m * ST2SZ) : (uint32_t)SBOFF;
}

// ---- prep kernels ----
__global__ void normalize_key_kernel(const float* __restrict__ key) {
    const int r = blockIdx.x;
    const int tid = threadIdx.x;  // 128
    const float* kr = key + (size_t)r * D_DIM;
    float v[4];
    float ss = 0.f;
#pragma unroll
    for (int i = 0; i < 4; ++i) { v[i] = kr[tid + i * 128]; ss += v[i] * v[i]; }
    __shared__ float ws[4];
    __shared__ float sinv;
#pragma unroll
    for (int o = 16; o > 0; o >>= 1) ss += __shfl_down_sync(0xffffffffu, ss, o);
    if ((tid & 31) == 0) ws[tid >> 5] = ss;
    __syncthreads();
    if (tid == 0) sinv = rsqrtf(ws[0] + ws[1] + ws[2] + ws[3] + 1e-12f);
    __syncthreads();
    const float iv = sinv;
#pragma unroll
    for (int i = 0; i < 4; ++i)
        g_Kh[(size_t)r * D_DIM + tid + i * 128] = __float2half(v[i] * iv);
}

__global__ void transpose_val_kernel(const float* __restrict__ val) {
    __shared__ float tile[32][33];
    const int ko = blockIdx.x * 32;
    const int no = blockIdx.y * 32;
    const int tx = threadIdx.x, ty = threadIdx.y;  // (32, 8)
#pragma unroll
    for (int j = 0; j < 32; j += 8)
        tile[ty + j][tx] = val[(size_t)(ko + ty + j) * C_DIM + no + tx];
    __syncthreads();
#pragma unroll
    for (int j = 0; j < 32; j += 8)
        g_Vt[(size_t)(no + ty + j) * C_DIM + ko + tx] = __float2half(tile[tx][ty + j]);
}

// ---- fused main kernel: 256 threads, 8 warps ----
__global__ __launch_bounds__(NTHREADS, 1)
void fused_kv_kernel(const float* __restrict__ query, float* __restrict__ out) {
    extern __shared__ char smem[];
    const uint32_t sb = smem_u32(smem);
    float* red = (float*)(smem + REDOFF);
    float* inv = (float*)(smem + INVOFF);

    const int tid  = threadIdx.x;
    const int lane = tid & 31;
    const int wid  = tid >> 5;
    const int wm   = wid >> 2;          // 0..1 (32 rows each)
    const int wn   = wid & 3;           // 0..3
    const int g    = lane >> 2;         // 0..7
    const int tig  = lane & 3;          // 0..3
    const int lrow = lane & 15;
    const int hs   = lane >> 4;         // k-half selector
    const int row0 = blockIdx.x * M_TILE;

    // ---- Step 0: load + l2-normalize Q tile into swizzled smem ----
    {
        const int r = tid >> 2;           // 0..63
        const int p = tid & 3;            // covers panels 2p, 2p+1
        const float* qrow = query + (size_t)(row0 + r) * D_DIM + p * 128;
        float ss = 0.f;
#pragma unroll
        for (int q = 0; q < 2; ++q) {
            char* pb = smem + QOFF + (2 * p + q) * 8192;
#pragma unroll 4
            for (int j = 0; j < 64; j += 4) {
                float4 v = *(const float4*)(qrow + q * 64 + j);
                ss += v.x * v.x + v.y * v.y + v.z * v.z + v.w * v.w;
                int b = r * 128 + j * 2;
                *(__half2*)(pb + SWZ(b))     = __floats2half2_rn(v.x, v.y);
                *(__half2*)(pb + SWZ(b + 4)) = __floats2half2_rn(v.z, v.w);
            }
        }
        red[tid] = ss;
        __syncthreads();
        if (tid < M_TILE)
            inv[tid] = rsqrtf(red[tid * 4] + red[tid * 4 + 1] +
                              red[tid * 4 + 2] + red[tid * 4 + 3] + 1e-12f);
        __syncthreads();
        const float qin = inv[r];
#pragma unroll
        for (int q = 0; q < 2; ++q) {
            char* pb = smem + QOFF + (2 * p + q) * 8192;
#pragma unroll 8
            for (int b = 0; b < 128; b += 4) {
                __half2* hp = (__half2*)(pb + SWZ(r * 128 + b));
                float2 f = __half22float2(*hp);
                *hp = __floats2half2_rn(f.x * qin, f.y * qin);
            }
        }
    }
    __syncthreads();

    // ---- GEMM1: W = sharp(Qn @ Kn^T), 64 iters (8 nc x 8 kc), 2-stage ----
    {
        float acc[2][4][4];
        fillB(g_Kh, D_DIM, sb + SBOFF, tid);
        CP_COMMIT();
        fillB(g_Kh + 64, D_DIM, sb + SBOFF + 16384, tid);
        CP_COMMIT();
        CP_WAIT1();
        __syncthreads();

#pragma unroll 1
        for (int t = 0; t < 64; ++t) {
            const int nc = t >> 3, kc = t & 7;
            if (kc == 0) {
#pragma unroll
                for (int mi = 0; mi < 2; ++mi)
#pragma unroll
                    for (int ni = 0; ni < 4; ++ni)
#pragma unroll
                        for (int e = 0; e < 4; ++e) acc[mi][ni][e] = 0.f;
            }
            const uint32_t sB = sb + SBOFF + (t & 1) * 16384;
            const uint32_t sA = sb + QOFF + kc * 8192;
#pragma unroll
            for (int ks = 0; ks < 4; ++ks) {
                unsigned a[2][4], b[4][2];
#pragma unroll
                for (int mi = 0; mi < 2; ++mi) {
                    int ar = wm * 32 + mi * 16 + lrow;
                    ldsm4(a[mi], sA + SWZ(ar * 128 + ks * 32 + hs * 16));
                }
#pragma unroll
                for (int pr = 0; pr < 2; ++pr) {
                    unsigned r4[4];
                    int nr = wn * 32 + pr * 16 + lrow;
                    ldsm4(r4, sB + SWZ(nr * 128 + ks * 32 + hs * 16));
                    b[pr * 2][0] = r4[0]; b[pr * 2 + 1][0] = r4[1];
                    b[pr * 2][1] = r4[2]; b[pr * 2 + 1][1] = r4[3];
                }
#pragma unroll
                for (int mi = 0; mi < 2; ++mi)
#pragma unroll
                    for (int ni = 0; ni < 4; ++ni)
                        mma16816(acc[mi][ni], a[mi], b[ni]);
            }
            if (kc == 7) {
#pragma unroll
                for (int mi = 0; mi < 2; ++mi) {
#pragma unroll
                    for (int ni = 0; ni < 4; ++ni) {
                        int rr = wm * 32 + mi * 16 + g;
                        int cc = nc * 128 + wn * 32 + ni * 8 + tig * 2;
                        int panel = cc >> 6, c6 = cc & 63;
                        char* base = smem + WOFF + panel * 8192;
                        *(__half2*)(base + SWZ(rr * 128 + c6 * 2)) =
                            __floats2half2_rn(sharp_fn(acc[mi][ni][0]), sharp_fn(acc[mi][ni][1]));
                        *(__half2*)(base + SWZ((rr + 8) * 128 + c6 * 2)) =
                            __floats2half2_rn(sharp_fn(acc[mi][ni][2]), sharp_fn(acc[mi][ni][3]));
                    }
                }
            }
            __syncthreads();
            if (t + 2 < 64) {
                int u = t + 2;
                fillB(g_Kh + (size_t)((u >> 3) * 128) * D_DIM + (u & 7) * 64, D_DIM,
                      sb + SBOFF + (u & 1) * 16384, tid);
            }
            CP_COMMIT();
            CP_WAIT1();
            __syncthreads();
        }
        CP_WAIT0();
        __syncthreads();
    }

    // ---- rowsum of W -> inv ----
    {
        const int r = tid >> 2, p = tid & 3;
        float s = 0.f;
#pragma unroll
        for (int q = 0; q < 4; ++q) {
            const uint4* rp = (const uint4*)(smem + WOFF + (p * 4 + q) * 8192 + r * 128);
#pragma unroll
            for (int i = 0; i < 8; ++i) {
                uint4 v = rp[i];
                const __half2* h2 = (const __half2*)&v;
#pragma unroll
                for (int j = 0; j < 4; ++j) {
                    float2 f = __half22float2(h2[j]);
                    s += f.x + f.y;
                }
            }
        }
        red[tid] = s;
        __syncthreads();
        if (tid < M_TILE)
            inv[tid] = 1.f / (red[tid * 4] + red[tid * 4 + 1] +
                              red[tid * 4 + 2] + red[tid * 4 + 3]);
        __syncthreads();
    }

    // ---- GEMM2: out = (1/rowsum) * W @ val ----
    // 64 iters (4 nc x 16 kc), warp tile 32x64, 3 rotating 32KB stages, one sync/iter
    {
        float acc[2][8][4];
        fillB2(g_Vt, C_DIM, sb + stage2_off(0), tid);
        CP_COMMIT();
        fillB2(g_Vt + 64, C_DIM, sb + stage2_off(1), tid);
        CP_COMMIT();
        CP_WAIT1();
        __syncthreads();

#pragma unroll 1
        for (int t = 0; t < 64; ++t) {
            const int nc = t >> 4, kc = t & 15;
            if (kc == 0) {
#pragma unroll
                for (int mi = 0; mi < 2; ++mi)
#pragma unroll
                    for (int ni = 0; ni < 8; ++ni)
#pragma unroll
                        for (int e = 0; e < 4; ++e) acc[mi][ni][e] = 0.f;
            }
            {
                int u = t + 2;
                if (u < 64)
                    fillB2(g_Vt + (size_t)((u >> 4) * 256) * C_DIM + (u & 15) * 64, C_DIM,
                           sb + stage2_off(u), tid);
                CP_COMMIT();
            }
            const uint32_t sB = sb + stage2_off(t);
            const uint32_t sA = sb + WOFF + kc * 8192;
#pragma unroll
            for (int ks = 0; ks < 4; ++ks) {
                unsigned a[2][4], b[8][2];
#pragma unroll
                for (int mi = 0; mi < 2; ++mi) {
                    int ar = wm * 32 + mi * 16 + lrow;
                    ldsm4(a[mi], sA + SWZ(ar * 128 + ks * 32 + hs * 16));
                }
#pragma unroll
                for (int pr = 0; pr < 4; ++pr) {
                    unsigned r4[4];
                    int nr = wn * 64 + pr * 16 + lrow;
                    ldsm4(r4, sB + SWZ(nr * 128 + ks * 32 + hs * 16));
                    b[pr * 2][0] = r4[0]; b[pr * 2 + 1][0] = r4[1];
                    b[pr * 2][1] = r4[2]; b[pr * 2 + 1][1] = r4[3];
                }
#pragma unroll
                for (int mi = 0; mi < 2; ++mi)
#pragma unroll
                    for (int ni = 0; ni < 8; ++ni)
                        mma16816(acc[mi][ni], a[mi], b[ni]);
            }
            if (kc == 15) {
#pragma unroll
                for (int mi = 0; mi < 2; ++mi) {
#pragma unroll
                    for (int ni = 0; ni < 8; ++ni) {
                        int rr = wm * 32 + mi * 16 + g;
                        int cc = nc * 256 + wn * 64 + ni * 8 + tig * 2;
                        float i0 = inv[rr], i8 = inv[rr + 8];
                        *(float2*)(out + (size_t)(row0 + rr) * C_DIM + cc) =
                            make_float2(acc[mi][ni][0] * i0, acc[mi][ni][1] * i0);
                        *(float2*)(out + (size_t)(row0 + rr + 8) * C_DIM + cc) =
                            make_float2(acc[mi][ni][2] * i8, acc[mi][ni][3] * i8);
                    }
                }
            }
            CP_WAIT1();
            __syncthreads();
        }
    }
}

// ---------------------------------------------------------------------------
extern "C" void kernel_launch(void* const* d_in, const int* in_sizes, int n_in,
                              void* d_out, int out_size) {
    const float* query = (const float*)d_in[0];
    const float* key   = (const float*)d_in[1];
    const float* val   = (const float*)d_in[2];
    float* out = (float*)d_out;

    const int B = in_sizes[0] / D_DIM;

    normalize_key_kernel<<<C_DIM, 128>>>(key);
    transpose_val_kernel<<<dim3(C_DIM / 32, C_DIM / 32), dim3(32, 8)>>>(val);

    cudaFuncSetAttribute(fused_kv_kernel,
                         cudaFuncAttributeMaxDynamicSharedMemorySize, SMEM_BYTES);
    fused_kv_kernel<<<B / M_TILE, NTHREADS, SMEM_BYTES>>>(query, out);
}

// round 9
// speedup vs baseline: 1.3235x; 1.0266x over previous
#include <cuda_runtime.h>
#include <cuda_fp16.h>
#include <cstdint>

#define D_DIM 512
#define C_DIM 1024
#define M_TILE 64
#define NTHREADS 256

// smem layout (bytes)
#define QOFF   0            // 64 x 512 fp16, 8 panels (64r x 128B) SW128; reused as GEMM2 stages 0,1
#define WOFF   65536        // 64 x 1024 fp16, 16 panels (64r x 128B) SW128
#define SBOFF  196608       // GEMM1: 2 x 16KB stages; GEMM2: stage 2 (32KB)
#define REDOFF 229376       // 256 floats
#define INVOFF 230400       // 64 floats
#define SMEM_BYTES 230656
#define ST2SZ  32768        // GEMM2 stage: 256 rows x 64 cols fp16

// ---- small device scratch (3 MiB total) ----
__device__ __half g_Kh[C_DIM * D_DIM];   // normalized keys fp16
__device__ __half g_Vt[C_DIM * C_DIM];   // val transposed fp16: g_Vt[n*C+k] = val[k*C+n]

// ---- helpers ----
__device__ __forceinline__ uint32_t smem_u32(const void* p) {
    uint32_t a;
    asm("{ .reg .u64 t; cvta.to.shared.u64 t, %1; cvt.u32.u64 %0, t; }" : "=r"(a) : "l"(p));
    return a;
}
#define SWZ(x) ((x) ^ (((x) >> 3) & 0x70))

__device__ __forceinline__ void cp16(uint32_t s, const void* g) {
    asm volatile("cp.async.cg.shared.global [%0], [%1], 16;" :: "r"(s), "l"(g));
}
#define CP_COMMIT() asm volatile("cp.async.commit_group;" ::: "memory")
#define CP_WAIT1()  asm volatile("cp.async.wait_group 1;" ::: "memory")
#define CP_WAIT0()  asm volatile("cp.async.wait_group 0;" ::: "memory")

__device__ __forceinline__ void ldsm4(unsigned r[4], uint32_t a) {
    asm volatile("ldmatrix.sync.aligned.m8n8.x4.shared.b16 {%0,%1,%2,%3}, [%4];"
                 : "=r"(r[0]), "=r"(r[1]), "=r"(r[2]), "=r"(r[3]) : "r"(a));
}
__device__ __forceinline__ void mma16816(float c[4], const unsigned a[4], const unsigned b[2]) {
    asm volatile(
        "mma.sync.aligned.m16n8k16.row.col.f32.f16.f16.f32 "
        "{%0,%1,%2,%3}, {%4,%5,%6,%7}, {%8,%9}, {%0,%1,%2,%3};\n"
        : "+f"(c[0]), "+f"(c[1]), "+f"(c[2]), "+f"(c[3])
        : "r"(a[0]), "r"(a[1]), "r"(a[2]), "r"(a[3]), "r"(b[0]), "r"(b[1]));
}

// sharp(x) = sigmoid(10x-5) + sigmoid(-10x-5)
__device__ __forceinline__ float sharp_fn(float x) {
    const float E = 148.4131591f;      // e^5
    const float E2p1 = 22027.4658f;    // e^10 + 1
    float u = __expf(10.f * x);
    float eu = E * u;
    float num = fmaf(eu, u, fmaf(2.f, u, E));
    float den = fmaf(eu, u, fmaf(E2p1, u, E));
    return __fdividef(num, den);
}

// GEMM1 stage: 128 rows x 64 cols fp16 (256 threads)
__device__ __forceinline__ void fillB(const __half* __restrict__ gsrc, int ldb,
                                      uint32_t dst, int tid) {
#pragma unroll
    for (int it = 0; it < 4; ++it) {
        int idx = it * NTHREADS + tid;
        int r = idx >> 3, c = idx & 7;
        cp16(dst + SWZ(r * 128 + c * 16), gsrc + (size_t)r * ldb + c * 8);
    }
}

// GEMM2 stage: 256 rows x 64 cols fp16 (256 threads)
__device__ __forceinline__ void fillB2(const __half* __restrict__ gsrc, int ldb,
                                       uint32_t dst, int tid) {
#pragma unroll
    for (int it = 0; it < 8; ++it) {
        int idx = it * NTHREADS + tid;
        int r = idx >> 3, c = idx & 7;
        cp16(dst + SWZ(r * 128 + c * 16), gsrc + (size_t)r * ldb + c * 8);
    }
}

// GEMM2 rotating stage base (3 distinct 32KB buffers)
__device__ __forceinline__ uint32_t stage2_off(int u) {
    int m = u % 3;
    return (m < 2) ? (uint32_t)(QOFF + m * ST2SZ) : (uint32_t)SBOFF;
}

// ---- prep kernels ----
__global__ void normalize_key_kernel(const float* __restrict__ key) {
    const int r = blockIdx.x;
    const int tid = threadIdx.x;  // 128
    const float* kr = key + (size_t)r * D_DIM;
    float v[4];
    float ss = 0.f;
#pragma unroll
    for (int i = 0; i < 4; ++i) { v[i] = kr[tid + i * 128]; ss += v[i] * v[i]; }
    __shared__ float ws[4];
    __shared__ float sinv;
#pragma unroll
    for (int o = 16; o > 0; o >>= 1) ss += __shfl_down_sync(0xffffffffu, ss, o);
    if ((tid & 31) == 0) ws[tid >> 5] = ss;
    __syncthreads();
    if (tid == 0) sinv = rsqrtf(ws[0] + ws[1] + ws[2] + ws[3] + 1e-12f);
    __syncthreads();
    const float iv = sinv;
#pragma unroll
    for (int i = 0; i < 4; ++i)
        g_Kh[(size_t)r * D_DIM + tid + i * 128] = __float2half(v[i] * iv);
}

__global__ void transpose_val_kernel(const float* __restrict__ val) {
    __shared__ float tile[32][33];
    const int ko = blockIdx.x * 32;
    const int no = blockIdx.y * 32;
    const int tx = threadIdx.x, ty = threadIdx.y;  // (32, 8)
#pragma unroll
    for (int j = 0; j < 32; j += 8)
        tile[ty + j][tx] = val[(size_t)(ko + ty + j) * C_DIM + no + tx];
    __syncthreads();
#pragma unroll
    for (int j = 0; j < 32; j += 8)
        g_Vt[(size_t)(no + ty + j) * C_DIM + ko + tx] = __float2half(tile[tx][ty + j]);
}

// ---- fused main kernel: 256 threads, 8 warps ----
__global__ __launch_bounds__(NTHREADS, 1)
void fused_kv_kernel(const float* __restrict__ query, float* __restrict__ out) {
    extern __shared__ char smem[];
    const uint32_t sb = smem_u32(smem);
    float* red = (float*)(smem + REDOFF);
    float* inv = (float*)(smem + INVOFF);

    const int tid  = threadIdx.x;
    const int lane = tid & 31;
    const int wid  = tid >> 5;
    const int wm   = wid >> 2;          // 0..1 (32 rows each)
    const int wn   = wid & 3;           // 0..3
    const int g    = lane >> 2;         // 0..7
    const int tig  = lane & 3;          // 0..3
    const int lrow = lane & 15;
    const int hs   = lane >> 4;         // k-half selector
    const int row0 = blockIdx.x * M_TILE;

    // ---- Step 0: load + l2-normalize Q tile into swizzled smem ----
    {
        const int r = tid >> 2;           // 0..63
        const int p = tid & 3;            // covers panels 2p, 2p+1
        const float* qrow = query + (size_t)(row0 + r) * D_DIM + p * 128;
        float ss = 0.f;
#pragma unroll
        for (int q = 0; q < 2; ++q) {
            char* pb = smem + QOFF + (2 * p + q) * 8192;
#pragma unroll 4
            for (int j = 0; j < 64; j += 4) {
                float4 v = *(const float4*)(qrow + q * 64 + j);
                ss += v.x * v.x + v.y * v.y + v.z * v.z + v.w * v.w;
                int b = r * 128 + j * 2;
                *(__half2*)(pb + SWZ(b))     = __floats2half2_rn(v.x, v.y);
                *(__half2*)(pb + SWZ(b + 4)) = __floats2half2_rn(v.z, v.w);
            }
        }
        red[tid] = ss;
        __syncthreads();
        if (tid < M_TILE)
            inv[tid] = rsqrtf(red[tid * 4] + red[tid * 4 + 1] +
                              red[tid * 4 + 2] + red[tid * 4 + 3] + 1e-12f);
        __syncthreads();
        const float qin = inv[r];
#pragma unroll
        for (int q = 0; q < 2; ++q) {
            char* pb = smem + QOFF + (2 * p + q) * 8192;
#pragma unroll 8
            for (int b = 0; b < 128; b += 4) {
                __half2* hp = (__half2*)(pb + SWZ(r * 128 + b));
                float2 f = __half22float2(*hp);
                *hp = __floats2half2_rn(f.x * qin, f.y * qin);
            }
        }
    }
    __syncthreads();
    // zero rowsum accumulators (first read/atomic is after in-loop syncs)
    if (tid < M_TILE) red[tid] = 0.f;

    // ---- GEMM1: W = sharp(Qn @ Kn^T), 64 iters (8 nc x 8 kc), 2-stage, 1 sync/iter ----
    {
        float acc[2][4][4];
        float rs[2][2] = {{0.f, 0.f}, {0.f, 0.f}};   // rowsum partials (mi, row-half)
        fillB(g_Kh, D_DIM, sb + SBOFF, tid);
        CP_COMMIT();

#pragma unroll 1
        for (int t = 0; t < 64; ++t) {
            const int nc = t >> 3, kc = t & 7;
            CP_WAIT0();
            __syncthreads();       // buf[t&1] ready everywhere; compute(t-1) done everywhere
            if (t + 1 < 64) {
                int u = t + 1;
                fillB(g_Kh + (size_t)((u >> 3) * 128) * D_DIM + (u & 7) * 64, D_DIM,
                      sb + SBOFF + (u & 1) * 16384, tid);
                CP_COMMIT();
            }
            if (kc == 0) {
#pragma unroll
                for (int mi = 0; mi < 2; ++mi)
#pragma unroll
                    for (int ni = 0; ni < 4; ++ni)
#pragma unroll
                        for (int e = 0; e < 4; ++e) acc[mi][ni][e] = 0.f;
            }
            const uint32_t sB = sb + SBOFF + (t & 1) * 16384;
            const uint32_t sA = sb + QOFF + kc * 8192;
#pragma unroll
            for (int ks = 0; ks < 4; ++ks) {
                unsigned a[2][4], b[4][2];
#pragma unroll
                for (int mi = 0; mi < 2; ++mi) {
                    int ar = wm * 32 + mi * 16 + lrow;
                    ldsm4(a[mi], sA + SWZ(ar * 128 + ks * 32 + hs * 16));
                }
#pragma unroll
                for (int pr = 0; pr < 2; ++pr) {
                    unsigned r4[4];
                    int nr = wn * 32 + pr * 16 + lrow;
                    ldsm4(r4, sB + SWZ(nr * 128 + ks * 32 + hs * 16));
                    b[pr * 2][0] = r4[0]; b[pr * 2 + 1][0] = r4[1];
                    b[pr * 2][1] = r4[2]; b[pr * 2 + 1][1] = r4[3];
                }
#pragma unroll
                for (int mi = 0; mi < 2; ++mi)
#pragma unroll
                    for (int ni = 0; ni < 4; ++ni)
                        mma16816(acc[mi][ni], a[mi], b[ni]);
            }
            if (kc == 7) {
#pragma unroll
                for (int mi = 0; mi < 2; ++mi) {
#pragma unroll
                    for (int ni = 0; ni < 4; ++ni) {
                        int rr = wm * 32 + mi * 16 + g;
                        int cc = nc * 128 + wn * 32 + ni * 8 + tig * 2;
                        int panel = cc >> 6, c6 = cc & 63;
                        char* base = smem + WOFF + panel * 8192;
                        float w0 = sharp_fn(acc[mi][ni][0]);
                        float w1 = sharp_fn(acc[mi][ni][1]);
                        float w2 = sharp_fn(acc[mi][ni][2]);
                        float w3 = sharp_fn(acc[mi][ni][3]);
                        rs[mi][0] += w0 + w1;
                        rs[mi][1] += w2 + w3;
                        *(__half2*)(base + SWZ(rr * 128 + c6 * 2)) = __floats2half2_rn(w0, w1);
                        *(__half2*)(base + SWZ((rr + 8) * 128 + c6 * 2)) = __floats2half2_rn(w2, w3);
                    }
                }
            }
        }
        // fold rowsums (f32) into shared accumulators
        atomicAdd(&red[wm * 32 + g],       rs[0][0]);
        atomicAdd(&red[wm * 32 + g + 8],   rs[0][1]);
        atomicAdd(&red[wm * 32 + 16 + g],  rs[1][0]);
        atomicAdd(&red[wm * 32 + 24 + g],  rs[1][1]);
        __syncthreads();
        if (tid < M_TILE) inv[tid] = 1.f / red[tid];
        __syncthreads();
    }

    // ---- GEMM2: out = (1/rowsum) * W @ val ----
    // 64 iters (4 nc x 16 kc), warp tile 32x64, 3 rotating 32KB stages, one sync/iter
    {
        float acc[2][8][4];
        fillB2(g_Vt, C_DIM, sb + stage2_off(0), tid);
        CP_COMMIT();
        fillB2(g_Vt + 64, C_DIM, sb + stage2_off(1), tid);
        CP_COMMIT();
        CP_WAIT1();
        __syncthreads();

#pragma unroll 1
        for (int t = 0; t < 64; ++t) {
            const int nc = t >> 4, kc = t & 15;
            if (kc == 0) {
#pragma unroll
                for (int mi = 0; mi < 2; ++mi)
#pragma unroll
                    for (int ni = 0; ni < 8; ++ni)
#pragma unroll
                        for (int e = 0; e < 4; ++e) acc[mi][ni][e] = 0.f;
            }
            {
                int u = t + 2;
                if (u < 64)
                    fillB2(g_Vt + (size_t)((u >> 4) * 256) * C_DIM + (u & 15) * 64, C_DIM,
                           sb + stage2_off(u), tid);
                CP_COMMIT();
            }
            const uint32_t sB = sb + stage2_off(t);
            const uint32_t sA = sb + WOFF + kc * 8192;
#pragma unroll
            for (int ks = 0; ks < 4; ++ks) {
                unsigned a[2][4], b[8][2];
#pragma unroll
                for (int mi = 0; mi < 2; ++mi) {
                    int ar = wm * 32 + mi * 16 + lrow;
                    ldsm4(a[mi], sA + SWZ(ar * 128 + ks * 32 + hs * 16));
                }
#pragma unroll
                for (int pr = 0; pr < 4; ++pr) {
                    unsigned r4[4];
                    int nr = wn * 64 + pr * 16 + lrow;
                    ldsm4(r4, sB + SWZ(nr * 128 + ks * 32 + hs * 16));
                    b[pr * 2][0] = r4[0]; b[pr * 2 + 1][0] = r4[1];
                    b[pr * 2][1] = r4[2]; b[pr * 2 + 1][1] = r4[3];
                }
#pragma unroll
                for (int mi = 0; mi < 2; ++mi)
#pragma unroll
                    for (int ni = 0; ni < 8; ++ni)
                        mma16816(acc[mi][ni], a[mi], b[ni]);
            }
            if (kc == 15) {
#pragma unroll
                for (int mi = 0; mi < 2; ++mi) {
#pragma unroll
                    for (int ni = 0; ni < 8; ++ni) {
                        int rr = wm * 32 + mi * 16 + g;
                        int cc = nc * 256 + wn * 64 + ni * 8 + tig * 2;
                        float i0 = inv[rr], i8 = inv[rr + 8];
                        *(float2*)(out + (size_t)(row0 + rr) * C_DIM + cc) =
                            make_float2(acc[mi][ni][0] * i0, acc[mi][ni][1] * i0);
                        *(float2*)(out + (size_t)(row0 + rr + 8) * C_DIM + cc) =
                            make_float2(acc[mi][ni][2] * i8, acc[mi][ni][3] * i8);
                    }
                }
            }
            CP_WAIT1();
            __syncthreads();
        }
    }
}

// ---------------------------------------------------------------------------
extern "C" void kernel_launch(void* const* d_in, const int* in_sizes, int n_in,
                              void* d_out, int out_size) {
    const float* query = (const float*)d_in[0];
    const float* key   = (const float*)d_in[1];
    const float* val   = (const float*)d_in[2];
    float* out = (float*)d_out;

    const int B = in_sizes[0] / D_DIM;

    normalize_key_kernel<<<C_DIM, 128>>>(key);
    transpose_val_kernel<<<dim3(C_DIM / 32, C_DIM / 32), dim3(32, 8)>>>(val);

    cudaFuncSetAttribute(fused_kv_kernel,
                         cudaFuncAttributeMaxDynamicSharedMemorySize, SMEM_BYTES);
    fused_kv_kernel<<<B / M_TILE, NTHREADS, SMEM_BYTES>>>(query, out);
}

// round 10
// speedup vs baseline: 1.3501x; 1.0201x over previous
#include <cuda_runtime.h>
#include <cuda_fp16.h>
#include <cstdint>

#define D_DIM 512
#define C_DIM 1024
#define M_TILE 64
#define NTHREADS 256

// smem layout (bytes)
#define QOFF   0            // 64 x 512 fp16 raw-q, 8 panels (64r x 128B) SW128; reused as GEMM2 stages 0,1
#define WOFF   65536        // 64 x 1024 fp16, 16 panels (64r x 128B) SW128
#define SBOFF  196608       // GEMM1: 2 x 16KB stages; GEMM2: stage 2 (32KB)
#define REDOFF 229376       // 256 floats
#define INVOFF 230400       // 64 floats
#define SMEM_BYTES 230656
#define ST2SZ  32768        // GEMM2 stage: 256 rows x 64 cols fp16

// ---- small device scratch (3 MiB) ----
__device__ __half g_Kh[C_DIM * D_DIM];   // normalized keys fp16
__device__ __half g_Vt[C_DIM * C_DIM];   // val transposed fp16: g_Vt[n*C+k] = val[k*C+n]

// ---- helpers ----
__device__ __forceinline__ uint32_t smem_u32(const void* p) {
    uint32_t a;
    asm("{ .reg .u64 t; cvta.to.shared.u64 t, %1; cvt.u32.u64 %0, t; }" : "=r"(a) : "l"(p));
    return a;
}
#define SWZ(x) ((x) ^ (((x) >> 3) & 0x70))

__device__ __forceinline__ void cp16(uint32_t s, const void* g) {
    asm volatile("cp.async.cg.shared.global [%0], [%1], 16;" :: "r"(s), "l"(g));
}
#define CP_COMMIT() asm volatile("cp.async.commit_group;" ::: "memory")
#define CP_WAIT1()  asm volatile("cp.async.wait_group 1;" ::: "memory")
#define CP_WAIT0()  asm volatile("cp.async.wait_group 0;" ::: "memory")

__device__ __forceinline__ void ldsm4(unsigned r[4], uint32_t a) {
    asm volatile("ldmatrix.sync.aligned.m8n8.x4.shared.b16 {%0,%1,%2,%3}, [%4];"
                 : "=r"(r[0]), "=r"(r[1]), "=r"(r[2]), "=r"(r[3]) : "r"(a));
}
__device__ __forceinline__ void mma16816(float c[4], const unsigned a[4], const unsigned b[2]) {
    asm volatile(
        "mma.sync.aligned.m16n8k16.row.col.f32.f16.f16.f32 "
        "{%0,%1,%2,%3}, {%4,%5,%6,%7}, {%8,%9}, {%0,%1,%2,%3};\n"
        : "+f"(c[0]), "+f"(c[1]), "+f"(c[2]), "+f"(c[3])
        : "r"(a[0]), "r"(a[1]), "r"(a[2]), "r"(a[3]), "r"(b[0]), "r"(b[1]));
}

// sharp(x) = sigmoid(10x-5) + sigmoid(-10x-5)
__device__ __forceinline__ float sharp_fn(float x) {
    const float E = 148.4131591f;      // e^5
    const float E2p1 = 22027.4658f;    // e^10 + 1
    float u = __expf(10.f * x);
    float eu = E * u;
    float num = fmaf(eu, u, fmaf(2.f, u, E));
    float den = fmaf(eu, u, fmaf(E2p1, u, E));
    return __fdividef(num, den);
}

// GEMM1 stage: 128 rows x 64 cols fp16 (256 threads)
__device__ __forceinline__ void fillB(const __half* __restrict__ gsrc, int ldb,
                                      uint32_t dst, int tid) {
#pragma unroll
    for (int it = 0; it < 4; ++it) {
        int idx = it * NTHREADS + tid;
        int r = idx >> 3, c = idx & 7;
        cp16(dst + SWZ(r * 128 + c * 16), gsrc + (size_t)r * ldb + c * 8);
    }
}

// GEMM2 stage: 256 rows x 64 cols fp16 (256 threads)
__device__ __forceinline__ void fillB2(const __half* __restrict__ gsrc, int ldb,
                                       uint32_t dst, int tid) {
#pragma unroll
    for (int it = 0; it < 8; ++it) {
        int idx = it * NTHREADS + tid;
        int r = idx >> 3, c = idx & 7;
        cp16(dst + SWZ(r * 128 + c * 16), gsrc + (size_t)r * ldb + c * 8);
    }
}

// GEMM2 rotating stage base (3 distinct 32KB buffers)
__device__ __forceinline__ uint32_t stage2_off(int u) {
    int m = u % 3;
    return (m < 2) ? (uint32_t)(QOFF + m * ST2SZ) : (uint32_t)SBOFF;
}

// fragment loaders
__device__ __forceinline__ void load_fr1(uint32_t sA, uint32_t sB, int ks,
                                         int wm, int wn, int lrow, int hs,
                                         unsigned a[2][4], unsigned b[4][2]) {
#pragma unroll
    for (int mi = 0; mi < 2; ++mi)
        ldsm4(a[mi], sA + SWZ((wm * 32 + mi * 16 + lrow) * 128 + ks * 32 + hs * 16));
#pragma unroll
    for (int pr = 0; pr < 2; ++pr) {
        unsigned r4[4];
        ldsm4(r4, sB + SWZ((wn * 32 + pr * 16 + lrow) * 128 + ks * 32 + hs * 16));
        b[pr * 2][0] = r4[0]; b[pr * 2 + 1][0] = r4[1];
        b[pr * 2][1] = r4[2]; b[pr * 2 + 1][1] = r4[3];
    }
}
__device__ __forceinline__ void load_fr2(uint32_t sA, uint32_t sB, int ks,
                                         int wm, int wn, int lrow, int hs,
                                         unsigned a[2][4], unsigned b[8][2]) {
#pragma unroll
    for (int mi = 0; mi < 2; ++mi)
        ldsm4(a[mi], sA + SWZ((wm * 32 + mi * 16 + lrow) * 128 + ks * 32 + hs * 16));
#pragma unroll
    for (int pr = 0; pr < 4; ++pr) {
        unsigned r4[4];
        ldsm4(r4, sB + SWZ((wn * 64 + pr * 16 + lrow) * 128 + ks * 32 + hs * 16));
        b[pr * 2][0] = r4[0]; b[pr * 2 + 1][0] = r4[1];
        b[pr * 2][1] = r4[2]; b[pr * 2 + 1][1] = r4[3];
    }
}

// ---- merged prep kernel: blocks [0,1024) transpose val, [1024,2048) normalize keys ----
__global__ void prep_kernel(const float* __restrict__ key, const float* __restrict__ val) {
    __shared__ float tile[32][33];
    __shared__ float ws[8];
    __shared__ float sinv;
    const int tid = threadIdx.x;
    if (blockIdx.x < 1024) {
        const int ko = (blockIdx.x & 31) * 32;
        const int no = (blockIdx.x >> 5) * 32;
        const int tx = tid & 31, ty = tid >> 5;   // (32, 8)
#pragma unroll
        for (int j = 0; j < 32; j += 8)
            tile[ty + j][tx] = val[(size_t)(ko + ty + j) * C_DIM + no + tx];
        __syncthreads();
#pragma unroll
        for (int j = 0; j < 32; j += 8)
            g_Vt[(size_t)(no + ty + j) * C_DIM + ko + tx] = __float2half(tile[tx][ty + j]);
    } else {
        const int r = blockIdx.x - 1024;
        const float* kr = key + (size_t)r * D_DIM;
        float v[2];
        float ss = 0.f;
#pragma unroll
        for (int i = 0; i < 2; ++i) { v[i] = kr[tid + i * 256]; ss += v[i] * v[i]; }
#pragma unroll
        for (int o = 16; o > 0; o >>= 1) ss += __shfl_down_sync(0xffffffffu, ss, o);
        if ((tid & 31) == 0) ws[tid >> 5] = ss;
        __syncthreads();
        if (tid == 0) {
            float s = 0.f;
#pragma unroll
            for (int j = 0; j < 8; ++j) s += ws[j];
            sinv = rsqrtf(s + 1e-12f);
        }
        __syncthreads();
        const float iv = sinv;
#pragma unroll
        for (int i = 0; i < 2; ++i)
            g_Kh[(size_t)r * D_DIM + tid + i * 256] = __float2half(v[i] * iv);
    }
}

// ---- fused main kernel: 256 threads, 8 warps ----
__global__ __launch_bounds__(NTHREADS, 1)
void fused_kv_kernel(const float* __restrict__ query, float* __restrict__ out) {
    extern __shared__ char smem[];
    const uint32_t sb = smem_u32(smem);
    float* red = (float*)(smem + REDOFF);
    float* inv = (float*)(smem + INVOFF);

    const int tid  = threadIdx.x;
    const int lane = tid & 31;
    const int wid  = tid >> 5;
    const int wm   = wid >> 2;          // 0..1 (32 rows each)
    const int wn   = wid & 3;           // 0..3
    const int g    = lane >> 2;         // 0..7
    const int tig  = lane & 3;          // 0..3
    const int lrow = lane & 15;
    const int hs   = lane >> 4;         // k-half selector
    const int row0 = blockIdx.x * M_TILE;

    // ---- Step 0: load RAW q -> fp16 smem (swizzled) + compute 1/||q|| ----
    {
        const int r = tid >> 2;           // 0..63
        const int p = tid & 3;            // covers panels 2p, 2p+1
        const float* qrow = query + (size_t)(row0 + r) * D_DIM + p * 128;
        float ss = 0.f;
#pragma unroll
        for (int q = 0; q < 2; ++q) {
            char* pb = smem + QOFF + (2 * p + q) * 8192;
#pragma unroll 4
            for (int j = 0; j < 64; j += 4) {
                float4 v = *(const float4*)(qrow + q * 64 + j);
                ss += v.x * v.x + v.y * v.y + v.z * v.z + v.w * v.w;
                int b = r * 128 + j * 2;
                *(__half2*)(pb + SWZ(b))     = __floats2half2_rn(v.x, v.y);
                *(__half2*)(pb + SWZ(b + 4)) = __floats2half2_rn(v.z, v.w);
            }
        }
        red[tid] = ss;
        __syncthreads();
        if (tid < M_TILE)
            inv[tid] = rsqrtf(red[tid * 4] + red[tid * 4 + 1] +
                              red[tid * 4 + 2] + red[tid * 4 + 3] + 1e-12f);
        __syncthreads();
    }
    // per-thread q-inverse norms for epilogue rows (sim = qinv * raw_acc)
    float qa[4];
#pragma unroll
    for (int j = 0; j < 4; ++j) qa[j] = inv[wm * 32 + j * 8 + g];
    __syncthreads();
    if (tid < M_TILE) red[tid] = 0.f;   // rowsum accumulators

    // ---- GEMM1: W = sharp(qinv * (q @ Kn^T)), 64 iters (8 nc x 8 kc), 2-stage ----
    {
        float acc[2][4][4];
        float rs[2][2] = {{0.f, 0.f}, {0.f, 0.f}};
        fillB(g_Kh, D_DIM, sb + SBOFF, tid);
        CP_COMMIT();

#pragma unroll 1
        for (int t = 0; t < 64; ++t) {
            const int nc = t >> 3, kc = t & 7;
            CP_WAIT0();
            __syncthreads();
            if (t + 1 < 64) {
                int u = t + 1;
                fillB(g_Kh + (size_t)((u >> 3) * 128) * D_DIM + (u & 7) * 64, D_DIM,
                      sb + SBOFF + (u & 1) * 16384, tid);
                CP_COMMIT();
            }
            if (kc == 0) {
#pragma unroll
                for (int mi = 0; mi < 2; ++mi)
#pragma unroll
                    for (int ni = 0; ni < 4; ++ni)
#pragma unroll
                        for (int e = 0; e < 4; ++e) acc[mi][ni][e] = 0.f;
            }
            const uint32_t sB = sb + SBOFF + (t & 1) * 16384;
            const uint32_t sA = sb + QOFF + kc * 8192;

            unsigned a[2][2][4], b[2][4][2];
            load_fr1(sA, sB, 0, wm, wn, lrow, hs, a[0], b[0]);
#pragma unroll
            for (int ks = 0; ks < 4; ++ks) {
                const int cur = ks & 1;
                if (ks < 3)
                    load_fr1(sA, sB, ks + 1, wm, wn, lrow, hs, a[cur ^ 1], b[cur ^ 1]);
#pragma unroll
                for (int mi = 0; mi < 2; ++mi)
#pragma unroll
                    for (int ni = 0; ni < 4; ++ni)
                        mma16816(acc[mi][ni], a[cur][mi], b[cur][ni]);
            }
            if (kc == 7) {
#pragma unroll
                for (int mi = 0; mi < 2; ++mi) {
#pragma unroll
                    for (int ni = 0; ni < 4; ++ni) {
                        int rr = wm * 32 + mi * 16 + g;
                        int cc = nc * 128 + wn * 32 + ni * 8 + tig * 2;
                        int panel = cc >> 6, c6 = cc & 63;
                        char* base = smem + WOFF + panel * 8192;
                        float w0 = sharp_fn(acc[mi][ni][0] * qa[mi * 2]);
                        float w1 = sharp_fn(acc[mi][ni][1] * qa[mi * 2]);
                        float w2 = sharp_fn(acc[mi][ni][2] * qa[mi * 2 + 1]);
                        float w3 = sharp_fn(acc[mi][ni][3] * qa[mi * 2 + 1]);
                        rs[mi][0] += w0 + w1;
                        rs[mi][1] += w2 + w3;
                        *(__half2*)(base + SWZ(rr * 128 + c6 * 2)) = __floats2half2_rn(w0, w1);
                        *(__half2*)(base + SWZ((rr + 8) * 128 + c6 * 2)) = __floats2half2_rn(w2, w3);
                    }
                }
            }
        }
        atomicAdd(&red[wm * 32 + g],       rs[0][0]);
        atomicAdd(&red[wm * 32 + g + 8],   rs[0][1]);
        atomicAdd(&red[wm * 32 + 16 + g],  rs[1][0]);
        atomicAdd(&red[wm * 32 + 24 + g],  rs[1][1]);
        __syncthreads();
        if (tid < M_TILE) inv[tid] = 1.f / red[tid];
        __syncthreads();
    }

    // ---- GEMM2: out = (1/rowsum) * W @ val ----
    // 64 iters (4 nc x 16 kc), warp tile 32x64, 3 rotating stages, wait-at-top (distance 2)
    {
        float acc[2][8][4];
        fillB2(g_Vt, C_DIM, sb + stage2_off(0), tid);
        CP_COMMIT();
        fillB2(g_Vt + 64, C_DIM, sb + stage2_off(1), tid);
        CP_COMMIT();

#pragma unroll 1
        for (int t = 0; t < 64; ++t) {
            const int nc = t >> 4, kc = t & 15;
            CP_WAIT1();
            __syncthreads();
            {
                int u = t + 2;
                if (u < 64) {
                    fillB2(g_Vt + (size_t)((u >> 4) * 256) * C_DIM + (u & 15) * 64, C_DIM,
                           sb + stage2_off(u), tid);
                    CP_COMMIT();
                }
            }
            if (kc == 0) {
#pragma unroll
                for (int mi = 0; mi < 2; ++mi)
#pragma unroll
                    for (int ni = 0; ni < 8; ++ni)
#pragma unroll
                        for (int e = 0; e < 4; ++e) acc[mi][ni][e] = 0.f;
            }
            const uint32_t sB = sb + stage2_off(t);
            const uint32_t sA = sb + WOFF + kc * 8192;

            unsigned a[2][2][4], b[2][8][2];
            load_fr2(sA, sB, 0, wm, wn, lrow, hs, a[0], b[0]);
#pragma unroll
            for (int ks = 0; ks < 4; ++ks) {
                const int cur = ks & 1;
                if (ks < 3)
                    load_fr2(sA, sB, ks + 1, wm, wn, lrow, hs, a[cur ^ 1], b[cur ^ 1]);
#pragma unroll
                for (int mi = 0; mi < 2; ++mi)
#pragma unroll
                    for (int ni = 0; ni < 8; ++ni)
                        mma16816(acc[mi][ni], a[cur][mi], b[cur][ni]);
            }
            if (kc == 15) {
#pragma unroll
                for (int mi = 0; mi < 2; ++mi) {
#pragma unroll
                    for (int ni = 0; ni < 8; ++ni) {
                        int rr = wm * 32 + mi * 16 + g;
                        int cc = nc * 256 + wn * 64 + ni * 8 + tig * 2;
                        float i0 = inv[rr], i8 = inv[rr + 8];
                        *(float2*)(out + (size_t)(row0 + rr) * C_DIM + cc) =
                            make_float2(acc[mi][ni][0] * i0, acc[mi][ni][1] * i0);
                        *(float2*)(out + (size_t)(row0 + rr + 8) * C_DIM + cc) =
                            make_float2(acc[mi][ni][2] * i8, acc[mi][ni][3] * i8);
                    }
                }
            }
        }
    }
}

// ---------------------------------------------------------------------------
extern "C" void kernel_launch(void* const* d_in, const int* in_sizes, int n_in,
                              void* d_out, int out_size) {
    const float* query = (const float*)d_in[0];
    const float* key   = (const float*)d_in[1];
    const float* val   = (const float*)d_in[2];
    float* out = (float*)d_out;

    const int B = in_sizes[0] / D_DIM;

    prep_kernel<<<2048, 256>>>(key, val);

    cudaFuncSetAttribute(fused_kv_kernel,
                         cudaFuncAttributeMaxDynamicSharedMemorySize, SMEM_BYTES);
    fused_kv_kernel<<<B / M_TILE, NTHREADS, SMEM_BYTES>>>(query, out);
}

// round 11
// speedup vs baseline: 1.3858x; 1.0265x over previous
#include <cuda_runtime.h>
#include <cuda_fp16.h>
#include <cstdint>

#define D_DIM 512
#define C_DIM 1024
#define M_TILE 64
#define NTHREADS 256

// smem layout (bytes)
#define QOFF   0            // 64 x 512 fp16 raw-q (8 panels SW128); GEMM2 stages 0,1
#define WOFF   65536        // W: 16 panels (64r x 128B) SW128; ALSO GEMM1 even-kc B stages (per-nc 32KB regions)
#define SBOFF  196608       // GEMM1 odd-kc B stage; GEMM2 stage 2 (32KB)
#define REDOFF 229376       // 256 floats
#define INVOFF 230400       // 64 floats
#define SMEM_BYTES 230656
#define ST2SZ  32768

// ---- small device scratch (3 MiB) ----
__device__ __half g_Kh[C_DIM * D_DIM];   // normalized keys fp16
__device__ __half g_Vt[C_DIM * C_DIM];   // val transposed fp16: g_Vt[n*C+k] = val[k*C+n]

// ---- helpers ----
__device__ __forceinline__ uint32_t smem_u32(const void* p) {
    uint32_t a;
    asm("{ .reg .u64 t; cvta.to.shared.u64 t, %1; cvt.u32.u64 %0, t; }" : "=r"(a) : "l"(p));
    return a;
}
#define SWZ(x) ((x) ^ (((x) >> 3) & 0x70))

__device__ __forceinline__ void cp16(uint32_t s, const void* g) {
    asm volatile("cp.async.cg.shared.global [%0], [%1], 16;" :: "r"(s), "l"(g));
}
#define CP_COMMIT() asm volatile("cp.async.commit_group;" ::: "memory")
#define CP_WAIT1()  asm volatile("cp.async.wait_group 1;" ::: "memory")
#define CP_WAIT0()  asm volatile("cp.async.wait_group 0;" ::: "memory")

__device__ __forceinline__ void ldsm4(unsigned r[4], uint32_t a) {
    asm volatile("ldmatrix.sync.aligned.m8n8.x4.shared.b16 {%0,%1,%2,%3}, [%4];"
                 : "=r"(r[0]), "=r"(r[1]), "=r"(r[2]), "=r"(r[3]) : "r"(a));
}
__device__ __forceinline__ void mma16816(float c[4], const unsigned a[4], const unsigned b[2]) {
    asm volatile(
        "mma.sync.aligned.m16n8k16.row.col.f32.f16.f16.f32 "
        "{%0,%1,%2,%3}, {%4,%5,%6,%7}, {%8,%9}, {%0,%1,%2,%3};\n"
        : "+f"(c[0]), "+f"(c[1]), "+f"(c[2]), "+f"(c[3])
        : "r"(a[0]), "r"(a[1]), "r"(a[2]), "r"(a[3]), "r"(b[0]), "r"(b[1]));
}

// sharp(x) = sigmoid(10x-5) + sigmoid(-10x-5)
__device__ __forceinline__ float sharp_fn(float x) {
    const float E = 148.4131591f;      // e^5
    const float E2p1 = 22027.4658f;    // e^10 + 1
    float u = __expf(10.f * x);
    float eu = E * u;
    float num = fmaf(eu, u, fmaf(2.f, u, E));
    float den = fmaf(eu, u, fmaf(E2p1, u, E));
    return __fdividef(num, den);
}

// stage fill: 256 rows x 64 cols fp16 (256 threads, 8 cp16 each)
__device__ __forceinline__ void fillB2(const __half* __restrict__ gsrc, int ldb,
                                       uint32_t dst, int tid) {
#pragma unroll
    for (int it = 0; it < 8; ++it) {
        int idx = it * NTHREADS + tid;
        int r = idx >> 3, c = idx & 7;
        cp16(dst + SWZ(r * 128 + c * 16), gsrc + (size_t)r * ldb + c * 8);
    }
}

// GEMM2 rotating stage base (3 distinct 32KB buffers)
__device__ __forceinline__ uint32_t stage2_off(int u) {
    int m = u % 3;
    return (m < 2) ? (uint32_t)(QOFF + m * ST2SZ) : (uint32_t)SBOFF;
}

// fragment loader: warp tile 32x64 (A 2 ldsm, B 4 ldsm -> 16 mma worth)
__device__ __forceinline__ void load_fr2(uint32_t sA, uint32_t sB, int ks,
                                         int wm, int wn, int lrow, int hs,
                                         unsigned a[2][4], unsigned b[8][2]) {
#pragma unroll
    for (int mi = 0; mi < 2; ++mi)
        ldsm4(a[mi], sA + SWZ((wm * 32 + mi * 16 + lrow) * 128 + ks * 32 + hs * 16));
#pragma unroll
    for (int pr = 0; pr < 4; ++pr) {
        unsigned r4[4];
        ldsm4(r4, sB + SWZ((wn * 64 + pr * 16 + lrow) * 128 + ks * 32 + hs * 16));
        b[pr * 2][0] = r4[0]; b[pr * 2 + 1][0] = r4[1];
        b[pr * 2][1] = r4[2]; b[pr * 2 + 1][1] = r4[3];
    }
}

// ---- merged prep kernel: blocks [0,1024) transpose val, [1024,2048) normalize keys ----
__global__ void prep_kernel(const float* __restrict__ key, const float* __restrict__ val) {
    __shared__ float tile[32][33];
    __shared__ float ws[8];
    __shared__ float sinv;
    const int tid = threadIdx.x;
    if (blockIdx.x < 1024) {
        const int ko = (blockIdx.x & 31) * 32;
        const int no = (blockIdx.x >> 5) * 32;
        const int tx = tid & 31, ty = tid >> 5;   // (32, 8)
#pragma unroll
        for (int j = 0; j < 32; j += 8)
            tile[ty + j][tx] = val[(size_t)(ko + ty + j) * C_DIM + no + tx];
        __syncthreads();
#pragma unroll
        for (int j = 0; j < 32; j += 8)
            g_Vt[(size_t)(no + ty + j) * C_DIM + ko + tx] = __float2half(tile[tx][ty + j]);
    } else {
        const int r = blockIdx.x - 1024;
        const float* kr = key + (size_t)r * D_DIM;
        float v[2];
        float ss = 0.f;
#pragma unroll
        for (int i = 0; i < 2; ++i) { v[i] = kr[tid + i * 256]; ss += v[i] * v[i]; }
#pragma unroll
        for (int o = 16; o > 0; o >>= 1) ss += __shfl_down_sync(0xffffffffu, ss, o);
        if ((tid & 31) == 0) ws[tid >> 5] = ss;
        __syncthreads();
        if (tid == 0) {
            float s = 0.f;
#pragma unroll
            for (int j = 0; j < 8; ++j) s += ws[j];
            sinv = rsqrtf(s + 1e-12f);
        }
        __syncthreads();
        const float iv = sinv;
#pragma unroll
        for (int i = 0; i < 2; ++i)
            g_Kh[(size_t)r * D_DIM + tid + i * 256] = __float2half(v[i] * iv);
    }
}

// ---- fused main kernel: 256 threads, 8 warps, warp tile 32x64 in both GEMMs ----
__global__ __launch_bounds__(NTHREADS, 1)
void fused_kv_kernel(const float* __restrict__ query, float* __restrict__ out) {
    extern __shared__ char smem[];
    const uint32_t sb = smem_u32(smem);
    float* red = (float*)(smem + REDOFF);
    float* inv = (float*)(smem + INVOFF);

    const int tid  = threadIdx.x;
    const int lane = tid & 31;
    const int wid  = tid >> 5;
    const int wm   = wid >> 2;          // 0..1 (32 rows each)
    const int wn   = wid & 3;           // 0..3 (64 cols each within 256-chunk)
    const int g    = lane >> 2;         // 0..7
    const int tig  = lane & 3;          // 0..3
    const int lrow = lane & 15;
    const int hs   = lane >> 4;
    const int row0 = blockIdx.x * M_TILE;

    // ---- Step 0: load RAW q -> fp16 smem (swizzled) + 1/||q|| ----
    {
        const int r = tid >> 2;
        const int p = tid & 3;
        const float* qrow = query + (size_t)(row0 + r) * D_DIM + p * 128;
        float ss = 0.f;
#pragma unroll
        for (int q = 0; q < 2; ++q) {
            char* pb = smem + QOFF + (2 * p + q) * 8192;
#pragma unroll 4
            for (int j = 0; j < 64; j += 4) {
                float4 v = *(const float4*)(qrow + q * 64 + j);
                ss += v.x * v.x + v.y * v.y + v.z * v.z + v.w * v.w;
                int b = r * 128 + j * 2;
                *(__half2*)(pb + SWZ(b))     = __floats2half2_rn(v.x, v.y);
                *(__half2*)(pb + SWZ(b + 4)) = __floats2half2_rn(v.z, v.w);
            }
        }
        red[tid] = ss;
        __syncthreads();
        if (tid < M_TILE)
            inv[tid] = rsqrtf(red[tid * 4] + red[tid * 4 + 1] +
                              red[tid * 4 + 2] + red[tid * 4 + 3] + 1e-12f);
        __syncthreads();
    }
    float qa[4];
#pragma unroll
    for (int j = 0; j < 4; ++j) qa[j] = inv[wm * 32 + j * 8 + g];
    __syncthreads();
    if (tid < M_TILE) red[tid] = 0.f;   // rowsum accumulators

    // ---- GEMM1: W = sharp(qinv * (q @ Kn^T)) ----
    // 32 iters (4 nc x 8 kc), N-chunk 256, warp tile 32x64.
    // Stages: even kc -> W(nc) region (WOFF + nc*32768, dead until nc's epilogue); odd kc -> SBOFF.
    {
        float acc[2][8][4];
        float rs[2][2] = {{0.f, 0.f}, {0.f, 0.f}};
        fillB2(g_Kh, D_DIM, sb + WOFF, tid);    // t=0: nc0 kc0 -> W(0)
        CP_COMMIT();

#pragma unroll 1
        for (int t = 0; t < 32; ++t) {
            const int nc = t >> 3, kc = t & 7;
            CP_WAIT0();
            __syncthreads();      // stage(t) ready; all reads of stage(t-1) (incl. W-region stages) done
            if (t + 1 < 32) {
                const int u = t + 1;
                const uint32_t dst = (u & 1) ? (uint32_t)SBOFF
                                             : (uint32_t)(WOFF + (u >> 3) * 32768);
                fillB2(g_Kh + (size_t)((u >> 3) * 256) * D_DIM + (u & 7) * 64, D_DIM,
                       sb + dst, tid);
                CP_COMMIT();
            }
            if (kc == 0) {
#pragma unroll
                for (int mi = 0; mi < 2; ++mi)
#pragma unroll
                    for (int ni = 0; ni < 8; ++ni)
#pragma unroll
                        for (int e = 0; e < 4; ++e) acc[mi][ni][e] = 0.f;
            }
            const uint32_t sB = sb + ((t & 1) ? (uint32_t)SBOFF
                                              : (uint32_t)(WOFF + nc * 32768));
            const uint32_t sA = sb + QOFF + kc * 8192;

            unsigned a[2][2][4], b[2][8][2];
            load_fr2(sA, sB, 0, wm, wn, lrow, hs, a[0], b[0]);
#pragma unroll
            for (int ks = 0; ks < 4; ++ks) {
                const int cur = ks & 1;
                if (ks < 3)
                    load_fr2(sA, sB, ks + 1, wm, wn, lrow, hs, a[cur ^ 1], b[cur ^ 1]);
#pragma unroll
                for (int mi = 0; mi < 2; ++mi)
#pragma unroll
                    for (int ni = 0; ni < 8; ++ni)
                        mma16816(acc[mi][ni], a[cur][mi], b[cur][ni]);
            }
            if (kc == 7) {
                // epilogue: sharpen -> W(nc) region (last read of W(nc)-as-stage was t-1, pre-sync)
#pragma unroll
                for (int mi = 0; mi < 2; ++mi) {
#pragma unroll
                    for (int ni = 0; ni < 8; ++ni) {
                        int rr = wm * 32 + mi * 16 + g;
                        int cc = nc * 256 + wn * 64 + ni * 8 + tig * 2;
                        int panel = cc >> 6, c6 = cc & 63;
                        char* base = smem + WOFF + panel * 8192;
                        float w0 = sharp_fn(acc[mi][ni][0] * qa[mi * 2]);
                        float w1 = sharp_fn(acc[mi][ni][1] * qa[mi * 2]);
                        float w2 = sharp_fn(acc[mi][ni][2] * qa[mi * 2 + 1]);
                        float w3 = sharp_fn(acc[mi][ni][3] * qa[mi * 2 + 1]);
                        rs[mi][0] += w0 + w1;
                        rs[mi][1] += w2 + w3;
                        *(__half2*)(base + SWZ(rr * 128 + c6 * 2)) = __floats2half2_rn(w0, w1);
                        *(__half2*)(base + SWZ((rr + 8) * 128 + c6 * 2)) = __floats2half2_rn(w2, w3);
                    }
                }
            }
        }
        atomicAdd(&red[wm * 32 + g],       rs[0][0]);
        atomicAdd(&red[wm * 32 + g + 8],   rs[0][1]);
        atomicAdd(&red[wm * 32 + 16 + g],  rs[1][0]);
        atomicAdd(&red[wm * 32 + 24 + g],  rs[1][1]);
        __syncthreads();
        if (tid < M_TILE) inv[tid] = 1.f / red[tid];
        __syncthreads();
    }

    // ---- GEMM2: out = (1/rowsum) * W @ val ----
    // 64 iters (4 nc x 16 kc), warp tile 32x64, 3 rotating stages, wait-at-top (distance 2)
    {
        float acc[2][8][4];
        fillB2(g_Vt, C_DIM, sb + stage2_off(0), tid);
        CP_COMMIT();
        fillB2(g_Vt + 64, C_DIM, sb + stage2_off(1), tid);
        CP_COMMIT();

#pragma unroll 1
        for (int t = 0; t < 64; ++t) {
            const int nc = t >> 4, kc = t & 15;
            CP_WAIT1();
            __syncthreads();
            {
                int u = t + 2;
                if (u < 64) {
                    fillB2(g_Vt + (size_t)((u >> 4) * 256) * C_DIM + (u & 15) * 64, C_DIM,
                           sb + stage2_off(u), tid);
                    CP_COMMIT();
                }
            }
            if (kc == 0) {
#pragma unroll
                for (int mi = 0; mi < 2; ++mi)
#pragma unroll
                    for (int ni = 0; ni < 8; ++ni)
#pragma unroll
                        for (int e = 0; e < 4; ++e) acc[mi][ni][e] = 0.f;
            }
            const uint32_t sB = sb + stage2_off(t);
            const uint32_t sA = sb + WOFF + kc * 8192;

            unsigned a[2][2][4], b[2][8][2];
            load_fr2(sA, sB, 0, wm, wn, lrow, hs, a[0], b[0]);
#pragma unroll
            for (int ks = 0; ks < 4; ++ks) {
                const int cur = ks & 1;
                if (ks < 3)
                    load_fr2(sA, sB, ks + 1, wm, wn, lrow, hs, a[cur ^ 1], b[cur ^ 1]);
#pragma unroll
                for (int mi = 0; mi < 2; ++mi)
#pragma unroll
                    for (int ni = 0; ni < 8; ++ni)
                        mma16816(acc[mi][ni], a[cur][mi], b[cur][ni]);
            }
            if (kc == 15) {
#pragma unroll
                for (int mi = 0; mi < 2; ++mi) {
#pragma unroll
                    for (int ni = 0; ni < 8; ++ni) {
                        int rr = wm * 32 + mi * 16 + g;
                        int cc = nc * 256 + wn * 64 + ni * 8 + tig * 2;
                        float i0 = inv[rr], i8 = inv[rr + 8];
                        *(float2*)(out + (size_t)(row0 + rr) * C_DIM + cc) =
                            make_float2(acc[mi][ni][0] * i0, acc[mi][ni][1] * i0);
                        *(float2*)(out + (size_t)(row0 + rr + 8) * C_DIM + cc) =
                            make_float2(acc[mi][ni][2] * i8, acc[mi][ni][3] * i8);
                    }
                }
            }
        }
    }
}

// ---------------------------------------------------------------------------
extern "C" void kernel_launch(void* const* d_in, const int* in_sizes, int n_in,
                              void* d_out, int out_size) {
    const float* query = (const float*)d_in[0];
    const float* key   = (const float*)d_in[1];
    const float* val   = (const float*)d_in[2];
    float* out = (float*)d_out;

    const int B = in_sizes[0] / D_DIM;

    prep_kernel<<<2048, 256>>>(key, val);

    cudaFuncSetAttribute(fused_kv_kernel,
                         cudaFuncAttributeMaxDynamicSharedMemorySize, SMEM_BYTES);
    fused_kv_kernel<<<B / M_TILE, NTHREADS, SMEM_BYTES>>>(query, out);
}